// round 7
// baseline (speedup 1.0000x reference)
#include <cuda_runtime.h>

#define MAXBLK 16384
#define BT 128
__device__ float g_part[MAXBLK];
__device__ unsigned g_ctr = 0;

// branch-free compare-exchange on (x,y) keyed by x
#define CE(xi, yi, xj, yj)                          \
    {                                               \
        bool p_ = (xi) > (xj);                      \
        float tx_ = (xi), ty_ = (yi);               \
        (xi) = p_ ? (xj) : (xi);                    \
        (yi) = p_ ? (yj) : (yi);                    \
        (xj) = p_ ? tx_ : (xj);                     \
        (yj) = p_ ? ty_ : (yj);                     \
    }

// uint compare-exchange: 2x IMNMX
#define CEU(a, b) { unsigned lo_ = umin(a, b), hi_ = umax(a, b); a = lo_; b = hi_; }

// Sortable key: diamond pseudo-angle (monotone bijection with atan2(y,x) on
// (-pi,pi], incl. the y==+/-0 edge cases), mapped to order-preserving uint,
// low 4 bits replaced by slot index for stable tiebreak in reference order.
__device__ __forceinline__ unsigned sort_key(float x, float y, unsigned j) {
    float s = fabsf(x) + fabsf(y);
    float r = __fdividef(x, s);
    float key = copysignf(1.f - r, y);   // y>0:(0,2], y<0:(-2,0), +/-0 at 0
    key = (s > 0.f) ? key : 0.f;         // vertex==centroid -> angle 0 (atan2(0,0)=0)
    unsigned u = __float_as_uint(key);
    u = ((int)u < 0) ? ~u : (u | 0x80000000u);
    return (u & ~15u) | j;
}

__global__ void __launch_bounds__(BT, 9)
k_loss(const float* __restrict__ pred, const float* __restrict__ target,
       float* __restrict__ out, int n, int nblk)
{
    __shared__ float2 sverts[16][BT];   // column layout: conflict-free dynamic idx
    const int tid = threadIdx.x;

    float loss = 0.f;
    for (int i = blockIdx.x * blockDim.x + tid; i < n; i += gridDim.x * blockDim.x) {
        const float* P = pred + 5l * i;
        const float* T = target + 5l * i;
        float px = P[0], py = P[1], pw = P[2], ph = P[3], pa = P[4];
        float tx = T[0], ty = T[1], tw = T[2], th = T[3], ta = T[4];
        float sp, cp, st, ct;
        __sincosf(pa, &sp, &cp);
        __sincosf(ta, &st, &ct);

        const float DX[4] = {0.5f, -0.5f, -0.5f, 0.5f};
        const float DY[4] = {0.5f, 0.5f, -0.5f, -0.5f};
        // Box1-centered frame (masks/area/residual all shift-invariant).
        float ox = tx - px, oy = ty - py;
        float c1x[4], c1y[4], c2x[4], c2y[4];
#pragma unroll
        for (int j = 0; j < 4; j++) {
            float dx = DX[j] * pw, dy = DY[j] * ph;
            c1x[j] = dx * cp - dy * sp;
            c1y[j] = dx * sp + dy * cp;
            float ex = DX[j] * tw, ey = DY[j] * th;
            c2x[j] = ex * ct - ey * st + ox;
            c2y[j] = ex * st + ey * ct + oy;
        }

        // ---- Collect valid vertices (reference order) into smem; sums in regs ----
        int kc = 0;
        float sx = 0.f, sy = 0.f;
        {   // corners of c1 inside box2 (division-free: compare dots vs eps*|e|^2)
            float ax = c2x[0], ay = c2y[0];
            float abx = c2x[1] - ax, aby = c2y[1] - ay;
            float adx = c2x[3] - ax, ady = c2y[3] - ay;
            float nab = abx * abx + aby * aby;
            float nad = adx * adx + ady * ady;
            float lab = -1e-6f * nab, hab = (1.f + 1e-6f) * nab;
            float lad = -1e-6f * nad, had = (1.f + 1e-6f) * nad;
#pragma unroll
            for (int j = 0; j < 4; j++) {
                float amx = c1x[j] - ax, amy = c1y[j] - ay;
                float dab = abx * amx + aby * amy;
                float dad = adx * amx + ady * amy;
                if (dab > lab && dab < hab && dad > lad && dad < had) {
                    sverts[kc][tid] = make_float2(c1x[j], c1y[j]);
                    sx += c1x[j]; sy += c1y[j]; kc++;
                }
            }
        }
        {   // corners of c2 inside box1
            float ax = c1x[0], ay = c1y[0];
            float abx = c1x[1] - ax, aby = c1y[1] - ay;
            float adx = c1x[3] - ax, ady = c1y[3] - ay;
            float nab = abx * abx + aby * aby;
            float nad = adx * adx + ady * ady;
            float lab = -1e-6f * nab, hab = (1.f + 1e-6f) * nab;
            float lad = -1e-6f * nad, had = (1.f + 1e-6f) * nad;
#pragma unroll
            for (int j = 0; j < 4; j++) {
                float amx = c2x[j] - ax, amy = c2y[j] - ay;
                float dab = abx * amx + aby * amy;
                float dad = adx * amx + ady * amy;
                if (dab > lab && dab < hab && dad > lad && dad < had) {
                    sverts[kc][tid] = make_float2(c2x[j], c2y[j]);
                    sx += c2x[j]; sy += c2y[j]; kc++;
                }
            }
        }
#pragma unroll
        for (int a = 0; a < 4; a++) {
            int a2 = (a + 1) & 3;
            float x1 = c1x[a], y1 = c1y[a];
            float ex = c1x[a2] - x1, ey = c1y[a2] - y1;
#pragma unroll
            for (int b = 0; b < 4; b++) {
                int b2 = (b + 1) & 3;
                float x3 = c2x[b], y3 = c2y[b];
                float fx = c2x[b2] - x3, fy = c2y[b2] - y3;
                float num = fy * ex - fx * ey;
                float dxs = x1 - x3, dys = y1 - y3;
                float den_t = fx * dys - fy * dxs;
                float den_u = ex * dys - ey * dxs;
                // t = den_t/num in (0,1) and u = -den_u/num in (0,1), sans division
                bool m = (den_t * num > 0.f) & ((den_t - num) * num < 0.f)
                       & (den_u * num < 0.f) & ((den_u + num) * num > 0.f);
                if (m && kc < 16) {
                    float t2 = __fdividef(den_t, num + 1e-8f);
                    float vx = fmaf(t2, ex, x1), vy = fmaf(t2, ey, y1);
                    sverts[kc][tid] = make_float2(vx, vy);
                    sx += vx; sy += vy; kc++;
                }
            }
        }

        // ---- Centroid, then sortable angle keys (registers, static indices) ----
        float invk = __fdividef(1.f, fmaxf((float)kc, 1.f));
        float mx = sx * invk, my = sy * invk;
        unsigned ky[16];
#pragma unroll
        for (int j = 0; j < 16; j++) ky[j] = 0xFFFFFFFFu;
#pragma unroll 16
        for (int j = 0; j < 16; j++) {
            if (j >= kc) break;
            float2 v = sverts[j][tid];
            ky[j] = sort_key(v.x - mx, v.y - my, (unsigned)j);
        }

        // ---- Batcher odd-even merge sort, 16 elems, 63 CEs, branch-free,
        //      unconditional (near-coincident boxes make kc>8 common) ----
        CEU(ky[0],ky[1]) CEU(ky[2],ky[3]) CEU(ky[4],ky[5]) CEU(ky[6],ky[7])
        CEU(ky[8],ky[9]) CEU(ky[10],ky[11]) CEU(ky[12],ky[13]) CEU(ky[14],ky[15])
        CEU(ky[0],ky[2]) CEU(ky[1],ky[3]) CEU(ky[4],ky[6]) CEU(ky[5],ky[7])
        CEU(ky[8],ky[10]) CEU(ky[9],ky[11]) CEU(ky[12],ky[14]) CEU(ky[13],ky[15])
        CEU(ky[1],ky[2]) CEU(ky[5],ky[6]) CEU(ky[9],ky[10]) CEU(ky[13],ky[14])
        CEU(ky[0],ky[4]) CEU(ky[1],ky[5]) CEU(ky[2],ky[6]) CEU(ky[3],ky[7])
        CEU(ky[8],ky[12]) CEU(ky[9],ky[13]) CEU(ky[10],ky[14]) CEU(ky[11],ky[15])
        CEU(ky[2],ky[4]) CEU(ky[3],ky[5]) CEU(ky[10],ky[12]) CEU(ky[11],ky[13])
        CEU(ky[1],ky[2]) CEU(ky[3],ky[4]) CEU(ky[5],ky[6])
        CEU(ky[9],ky[10]) CEU(ky[11],ky[12]) CEU(ky[13],ky[14])
        CEU(ky[0],ky[8]) CEU(ky[1],ky[9]) CEU(ky[2],ky[10]) CEU(ky[3],ky[11])
        CEU(ky[4],ky[12]) CEU(ky[5],ky[13]) CEU(ky[6],ky[14]) CEU(ky[7],ky[15])
        CEU(ky[4],ky[8]) CEU(ky[5],ky[9]) CEU(ky[6],ky[10]) CEU(ky[7],ky[11])
        CEU(ky[2],ky[4]) CEU(ky[3],ky[5]) CEU(ky[6],ky[8]) CEU(ky[7],ky[9])
        CEU(ky[10],ky[12]) CEU(ky[11],ky[13])
        CEU(ky[1],ky[2]) CEU(ky[3],ky[4]) CEU(ky[5],ky[6]) CEU(ky[7],ky[8])
        CEU(ky[9],ky[10]) CEU(ky[11],ky[12]) CEU(ky[13],ky[14])

        // ---- Shoelace over sorted valid vertices ----
        float area2 = 0.f;
        float v0x = 0.f, v0y = 0.f, pvx = 0.f, pvy = 0.f;
#pragma unroll 16
        for (int j = 0; j < 16; j++) {
            if (j >= kc) break;
            float2 v = sverts[ky[j] & 15u][tid];
            if (j == 0) { v0x = v.x; v0y = v.y; }
            else area2 += pvx * v.y - pvy * v.x;
            pvx = v.x; pvy = v.y;
        }
        area2 += pvx * v0y - pvy * v0x;
        float inter = fabsf(area2) * 0.5f;

        float iou = __fdividef(inter, pw * ph + tw * th - inter);
        iou = fmaxf(iou, 1e-6f);

        // ---- Residual: x-sort corners of each box (5-CE networks) ----
        float ax0 = c1x[0], ay0 = c1y[0], ax1 = c1x[1], ay1 = c1y[1];
        float ax2 = c1x[2], ay2 = c1y[2], ax3 = c1x[3], ay3 = c1y[3];
        CE(ax0, ay0, ax1, ay1) CE(ax2, ay2, ax3, ay3)
        CE(ax0, ay0, ax2, ay2) CE(ax1, ay1, ax3, ay3)
        CE(ax1, ay1, ax2, ay2)
        float bx0 = c2x[0], by0 = c2y[0], bx1 = c2x[1], by1 = c2y[1];
        float bx2 = c2x[2], by2 = c2y[2], bx3 = c2x[3], by3 = c2y[3];
        CE(bx0, by0, bx1, by1) CE(bx2, by2, bx3, by3)
        CE(bx0, by0, bx2, by2) CE(bx1, by1, bx3, by3)
        CE(bx1, by1, bx2, by2)

        float d0 = bx0 - ax0;
        float d = 2.f * d0 * d0;
        float q1x = ax1 - bx1, q1y = ay1 - by1;
        float q2x = ax2 - bx2, q2y = ay2 - by2;
        float q3x = ax3 - bx3, q3y = ay3 - by3;
        d += q1x * q1x + q1y * q1y;
        d += q2x * q2x + q2y * q2y;
        d += q3x * q3x + q3y * q3y;
        float res = d * (1.f / (4.f * 1024.f * 1024.f));
        loss += 1.f - iou + res;
    }

    // ---- Block reduction -> per-block partial ----
#pragma unroll
    for (int o = 16; o > 0; o >>= 1)
        loss += __shfl_down_sync(0xffffffffu, loss, o);
    __shared__ float ssum[4];
    __shared__ bool is_last;
    int lane = threadIdx.x & 31, wid = threadIdx.x >> 5;
    if (lane == 0) ssum[wid] = loss;
    __syncthreads();
    if (threadIdx.x == 0) {
        float v = ssum[0] + ssum[1] + ssum[2] + ssum[3];
        g_part[blockIdx.x] = v;
        __threadfence();
        unsigned old = atomicAdd(&g_ctr, 1u);
        is_last = (old == (unsigned)(gridDim.x - 1));
    }
    __syncthreads();

    // ---- Last block finalizes (single kernel, graph-replay safe) ----
    if (is_last) {
        double s = 0.0;
        for (int j = threadIdx.x; j < nblk; j += blockDim.x)
            s += (double)__ldcg(&g_part[j]);
        __shared__ double sd[BT];
        sd[threadIdx.x] = s;
        __syncthreads();
#pragma unroll
        for (int o = BT / 2; o > 0; o >>= 1) {
            if (threadIdx.x < o) sd[threadIdx.x] += sd[threadIdx.x + o];
            __syncthreads();
        }
        if (threadIdx.x == 0) {
            out[0] = (float)(sd[0] / (double)n);
            g_ctr = 0;  // reset for next graph replay
        }
    }
}

extern "C" void kernel_launch(void* const* d_in, const int* in_sizes, int n_in,
                              void* d_out, int out_size)
{
    (void)n_in; (void)out_size;
    const float* pred = (const float*)d_in[0];
    const float* target = (const float*)d_in[1];
    int n = in_sizes[0] / 5;
    int blocks = (n + BT - 1) / BT;
    if (blocks > MAXBLK) blocks = MAXBLK;  // grid-stride covers remainder
    k_loss<<<blocks, BT>>>(pred, target, (float*)d_out, n, blocks);
}

// round 9
// speedup vs baseline: 1.3874x; 1.3874x over previous
#include <cuda_runtime.h>

#define MAXBLK 16384
#define BT 256
__device__ float g_part[MAXBLK];
__device__ unsigned g_ctr = 0;

// branch-free compare-exchange on (x,y) keyed by x
#define CE(xi, yi, xj, yj)                          \
    {                                               \
        bool p_ = (xi) > (xj);                      \
        float tx_ = (xi), ty_ = (yi);               \
        (xi) = p_ ? (xj) : (xi);                    \
        (yi) = p_ ? (yj) : (yi);                    \
        (xj) = p_ ? tx_ : (xj);                     \
        (yj) = p_ ? ty_ : (yj);                     \
    }

// uint compare-exchange: 2x IMNMX
#define CEU(a, b) { unsigned lo_ = umin(a, b), hi_ = umax(a, b); a = lo_; b = hi_; }

// Sortable key: diamond pseudo-angle (monotone bijection with atan2(y,x) on
// (-pi,pi], incl. the y==+/-0 edge cases), mapped to order-preserving uint,
// low 4 bits replaced by slot index for stable tiebreak in reference order.
__device__ __forceinline__ unsigned sort_key(float x, float y, unsigned j) {
    float s = fabsf(x) + fabsf(y);
    float r = __fdividef(x, s);
    float key = copysignf(1.f - r, y);   // y>0:(0,2], y<0:(-2,0), +/-0 at 0
    key = (s > 0.f) ? key : 0.f;         // vertex==centroid -> angle 0 (atan2(0,0)=0)
    unsigned u = __float_as_uint(key);
    u = ((int)u < 0) ? ~u : (u | 0x80000000u);
    return (u & ~15u) | j;
}

__global__ void __launch_bounds__(BT)
k_loss(const float* __restrict__ pred, const float* __restrict__ target,
       float* __restrict__ out, int n, int nblk)
{
    __shared__ float2 sverts[16][BT];   // column layout: conflict-free dynamic idx
    const int tid = threadIdx.x;

    float loss = 0.f;
    for (int i = blockIdx.x * blockDim.x + tid; i < n; i += gridDim.x * blockDim.x) {
        const float* P = pred + 5l * i;
        const float* T = target + 5l * i;
        float px = P[0], py = P[1], pw = P[2], ph = P[3], pa = P[4];
        float tx = T[0], ty = T[1], tw = T[2], th = T[3], ta = T[4];
        float sp, cp, st, ct;
        __sincosf(pa, &sp, &cp);
        __sincosf(ta, &st, &ct);

        const float DX[4] = {0.5f, -0.5f, -0.5f, 0.5f};
        const float DY[4] = {0.5f, 0.5f, -0.5f, -0.5f};
        // Box1-centered frame (masks/area/residual all shift-invariant).
        float ox = tx - px, oy = ty - py;
        float c1x[4], c1y[4], c2x[4], c2y[4];
#pragma unroll
        for (int j = 0; j < 4; j++) {
            float dx = DX[j] * pw, dy = DY[j] * ph;
            c1x[j] = dx * cp - dy * sp;
            c1y[j] = dx * sp + dy * cp;
            float ex = DX[j] * tw, ey = DY[j] * th;
            c2x[j] = ex * ct - ey * st + ox;
            c2y[j] = ex * st + ey * ct + oy;
        }

        // ---- Collect valid vertices (reference order) into smem; sums in regs ----
        int kc = 0;
        float sx = 0.f, sy = 0.f;
        {   // corners of c1 inside box2 (division-free: compare dots vs eps*|e|^2)
            float ax = c2x[0], ay = c2y[0];
            float abx = c2x[1] - ax, aby = c2y[1] - ay;
            float adx = c2x[3] - ax, ady = c2y[3] - ay;
            float nab = abx * abx + aby * aby;
            float nad = adx * adx + ady * ady;
            float lab = -1e-6f * nab, hab = (1.f + 1e-6f) * nab;
            float lad = -1e-6f * nad, had = (1.f + 1e-6f) * nad;
#pragma unroll
            for (int j = 0; j < 4; j++) {
                float amx = c1x[j] - ax, amy = c1y[j] - ay;
                float dab = abx * amx + aby * amy;
                float dad = adx * amx + ady * amy;
                if (dab > lab && dab < hab && dad > lad && dad < had) {
                    sverts[kc][tid] = make_float2(c1x[j], c1y[j]);
                    sx += c1x[j]; sy += c1y[j]; kc++;
                }
            }
        }
        {   // corners of c2 inside box1
            float ax = c1x[0], ay = c1y[0];
            float abx = c1x[1] - ax, aby = c1y[1] - ay;
            float adx = c1x[3] - ax, ady = c1y[3] - ay;
            float nab = abx * abx + aby * aby;
            float nad = adx * adx + ady * ady;
            float lab = -1e-6f * nab, hab = (1.f + 1e-6f) * nab;
            float lad = -1e-6f * nad, had = (1.f + 1e-6f) * nad;
#pragma unroll
            for (int j = 0; j < 4; j++) {
                float amx = c2x[j] - ax, amy = c2y[j] - ay;
                float dab = abx * amx + aby * amy;
                float dad = adx * amx + ady * amy;
                if (dab > lab && dab < hab && dad > lad && dad < had) {
                    sverts[kc][tid] = make_float2(c2x[j], c2y[j]);
                    sx += c2x[j]; sy += c2y[j]; kc++;
                }
            }
        }
#pragma unroll
        for (int a = 0; a < 4; a++) {
            int a2 = (a + 1) & 3;
            float x1 = c1x[a], y1 = c1y[a];
            float ex = c1x[a2] - x1, ey = c1y[a2] - y1;
#pragma unroll
            for (int b = 0; b < 4; b++) {
                int b2 = (b + 1) & 3;
                float x3 = c2x[b], y3 = c2y[b];
                float fx = c2x[b2] - x3, fy = c2y[b2] - y3;
                float num = fy * ex - fx * ey;
                float dxs = x1 - x3, dys = y1 - y3;
                float den_t = fx * dys - fy * dxs;
                float den_u = ex * dys - ey * dxs;
                // t = den_t/num in (0,1) and u = -den_u/num in (0,1), sans division
                bool m = (den_t * num > 0.f) & ((den_t - num) * num < 0.f)
                       & (den_u * num < 0.f) & ((den_u + num) * num > 0.f);
                if (m && kc < 16) {
                    float t2 = __fdividef(den_t, num + 1e-8f);
                    float vx = fmaf(t2, ex, x1), vy = fmaf(t2, ey, y1);
                    sverts[kc][tid] = make_float2(vx, vy);
                    sx += vx; sy += vy; kc++;
                }
            }
        }

        // ---- Centroid, then sortable angle keys (registers, static indices) ----
        float invk = __fdividef(1.f, fmaxf((float)kc, 1.f));
        float mx = sx * invk, my = sy * invk;
        unsigned ky[16];
#pragma unroll
        for (int j = 0; j < 16; j++) ky[j] = 0xFFFFFFFFu;
#pragma unroll 16
        for (int j = 0; j < 16; j++) {
            if (j >= kc) break;
            float2 v = sverts[j][tid];
            ky[j] = sort_key(v.x - mx, v.y - my, (unsigned)j);
        }

        // ---- Sort keys: 8-net (19 CE) fast path for kc<=8 (measured win),
        //      full 16-net (63 CE) fallback; both exact (pads sort high) ----
        if (kc <= 8) {
            CEU(ky[0],ky[1]) CEU(ky[2],ky[3]) CEU(ky[4],ky[5]) CEU(ky[6],ky[7])
            CEU(ky[0],ky[2]) CEU(ky[1],ky[3]) CEU(ky[4],ky[6]) CEU(ky[5],ky[7])
            CEU(ky[1],ky[2]) CEU(ky[5],ky[6])
            CEU(ky[0],ky[4]) CEU(ky[1],ky[5]) CEU(ky[2],ky[6]) CEU(ky[3],ky[7])
            CEU(ky[2],ky[4]) CEU(ky[3],ky[5])
            CEU(ky[1],ky[2]) CEU(ky[3],ky[4]) CEU(ky[5],ky[6])
        } else {
            CEU(ky[0],ky[1]) CEU(ky[2],ky[3]) CEU(ky[4],ky[5]) CEU(ky[6],ky[7])
            CEU(ky[8],ky[9]) CEU(ky[10],ky[11]) CEU(ky[12],ky[13]) CEU(ky[14],ky[15])
            CEU(ky[0],ky[2]) CEU(ky[1],ky[3]) CEU(ky[4],ky[6]) CEU(ky[5],ky[7])
            CEU(ky[8],ky[10]) CEU(ky[9],ky[11]) CEU(ky[12],ky[14]) CEU(ky[13],ky[15])
            CEU(ky[1],ky[2]) CEU(ky[5],ky[6]) CEU(ky[9],ky[10]) CEU(ky[13],ky[14])
            CEU(ky[0],ky[4]) CEU(ky[1],ky[5]) CEU(ky[2],ky[6]) CEU(ky[3],ky[7])
            CEU(ky[8],ky[12]) CEU(ky[9],ky[13]) CEU(ky[10],ky[14]) CEU(ky[11],ky[15])
            CEU(ky[2],ky[4]) CEU(ky[3],ky[5]) CEU(ky[10],ky[12]) CEU(ky[11],ky[13])
            CEU(ky[1],ky[2]) CEU(ky[3],ky[4]) CEU(ky[5],ky[6])
            CEU(ky[9],ky[10]) CEU(ky[11],ky[12]) CEU(ky[13],ky[14])
            CEU(ky[0],ky[8]) CEU(ky[1],ky[9]) CEU(ky[2],ky[10]) CEU(ky[3],ky[11])
            CEU(ky[4],ky[12]) CEU(ky[5],ky[13]) CEU(ky[6],ky[14]) CEU(ky[7],ky[15])
            CEU(ky[4],ky[8]) CEU(ky[5],ky[9]) CEU(ky[6],ky[10]) CEU(ky[7],ky[11])
            CEU(ky[2],ky[4]) CEU(ky[3],ky[5]) CEU(ky[6],ky[8]) CEU(ky[7],ky[9])
            CEU(ky[10],ky[12]) CEU(ky[11],ky[13])
            CEU(ky[1],ky[2]) CEU(ky[3],ky[4]) CEU(ky[5],ky[6]) CEU(ky[7],ky[8])
            CEU(ky[9],ky[10]) CEU(ky[11],ky[12]) CEU(ky[13],ky[14])
        }

        // ---- Shoelace over sorted valid vertices ----
        float area2 = 0.f;
        float v0x = 0.f, v0y = 0.f, pvx = 0.f, pvy = 0.f;
#pragma unroll 16
        for (int j = 0; j < 16; j++) {
            if (j >= kc) break;
            float2 v = sverts[ky[j] & 15u][tid];
            if (j == 0) { v0x = v.x; v0y = v.y; }
            else area2 += pvx * v.y - pvy * v.x;
            pvx = v.x; pvy = v.y;
        }
        area2 += pvx * v0y - pvy * v0x;
        float inter = fabsf(area2) * 0.5f;

        float iou = __fdividef(inter, pw * ph + tw * th - inter);
        iou = fmaxf(iou, 1e-6f);

        // ---- Residual: x-sort corners of each box (5-CE networks) ----
        float ax0 = c1x[0], ay0 = c1y[0], ax1 = c1x[1], ay1 = c1y[1];
        float ax2 = c1x[2], ay2 = c1y[2], ax3 = c1x[3], ay3 = c1y[3];
        CE(ax0, ay0, ax1, ay1) CE(ax2, ay2, ax3, ay3)
        CE(ax0, ay0, ax2, ay2) CE(ax1, ay1, ax3, ay3)
        CE(ax1, ay1, ax2, ay2)
        float bx0 = c2x[0], by0 = c2y[0], bx1 = c2x[1], by1 = c2y[1];
        float bx2 = c2x[2], by2 = c2y[2], bx3 = c2x[3], by3 = c2y[3];
        CE(bx0, by0, bx1, by1) CE(bx2, by2, bx3, by3)
        CE(bx0, by0, bx2, by2) CE(bx1, by1, bx3, by3)
        CE(bx1, by1, bx2, by2)

        float d0 = bx0 - ax0;
        float d = 2.f * d0 * d0;
        float q1x = ax1 - bx1, q1y = ay1 - by1;
        float q2x = ax2 - bx2, q2y = ay2 - by2;
        float q3x = ax3 - bx3, q3y = ay3 - by3;
        d += q1x * q1x + q1y * q1y;
        d += q2x * q2x + q2y * q2y;
        d += q3x * q3x + q3y * q3y;
        float res = d * (1.f / (4.f * 1024.f * 1024.f));
        loss += 1.f - iou + res;
    }

    // ---- Block reduction -> per-block partial ----
#pragma unroll
    for (int o = 16; o > 0; o >>= 1)
        loss += __shfl_down_sync(0xffffffffu, loss, o);
    __shared__ float ssum[8];
    __shared__ bool is_last;
    int lane = threadIdx.x & 31, wid = threadIdx.x >> 5;
    if (lane == 0) ssum[wid] = loss;
    __syncthreads();
    if (threadIdx.x == 0) {
        float v = 0.f;
#pragma unroll
        for (int w = 0; w < 8; w++) v += ssum[w];
        g_part[blockIdx.x] = v;
        __threadfence();
        unsigned old = atomicAdd(&g_ctr, 1u);
        is_last = (old == (unsigned)(gridDim.x - 1));
    }
    __syncthreads();

    // ---- Last block finalizes (single kernel, graph-replay safe) ----
    if (is_last) {
        double s = 0.0;
        for (int j = threadIdx.x; j < nblk; j += blockDim.x)
            s += (double)__ldcg(&g_part[j]);
        __shared__ double sd[BT];
        sd[threadIdx.x] = s;
        __syncthreads();
#pragma unroll
        for (int o = BT / 2; o > 0; o >>= 1) {
            if (threadIdx.x < o) sd[threadIdx.x] += sd[threadIdx.x + o];
            __syncthreads();
        }
        if (threadIdx.x == 0) {
            out[0] = (float)(sd[0] / (double)n);
            g_ctr = 0;  // reset for next graph replay
        }
    }
}

extern "C" void kernel_launch(void* const* d_in, const int* in_sizes, int n_in,
                              void* d_out, int out_size)
{
    (void)n_in; (void)out_size;
    const float* pred = (const float*)d_in[0];
    const float* target = (const float*)d_in[1];
    int n = in_sizes[0] / 5;
    int blocks = (n + BT - 1) / BT;
    if (blocks > MAXBLK) blocks = MAXBLK;  // grid-stride covers remainder
    k_loss<<<blocks, BT>>>(pred, target, (float*)d_out, n, blocks);
}